// round 15
// baseline (speedup 1.0000x reference)
#include <cuda_runtime.h>
#include <cuda_bf16.h>
#include <cuda_fp16.h>
#include <cstdint>

#define NN     4096
#define DM     128
#define QK     32
#define HEADS  8

// ---------------- device scratch (no allocation allowed) ----------------
__device__ static __half         g_xh[NN * 128];                  // x fp16
__device__ static __half         g_qh[NN * 256];                  // Q*qs fp16 [node][h*32+d]
__device__ static __half         g_kh[NN * 256];                  // K fp16
__device__ static __half         g_vt[(size_t)1024 * NN];         // [h*128+d][node], fp16
__device__ static __half         g_attnh[(size_t)NN * 1024];      // attention out, fp16
__device__ static __half         g_wqt[256 * 128];                // W^T fp16 [out][in]
__device__ static __half         g_wkt[256 * 128];
__device__ static __half         g_wvt[1024 * 128];
__device__ static __half         g_wot[128 * 1024];
__device__ static unsigned       g_maskbits[(NN / 32) * NN];      // [wordIdx][row]
__device__ static int            g_mask_mode;

// ---------------- helpers ----------------
__device__ __forceinline__ void mma_f16(float* d, const uint32_t* a, uint32_t b0, uint32_t b1)
{
    asm volatile("mma.sync.aligned.m16n8k16.row.col.f32.f16.f16.f32 "
                 "{%0,%1,%2,%3}, {%4,%5,%6,%7}, {%8,%9}, {%0,%1,%2,%3};"
                 : "+f"(d[0]), "+f"(d[1]), "+f"(d[2]), "+f"(d[3])
                 : "r"(a[0]), "r"(a[1]), "r"(a[2]), "r"(a[3]), "r"(b0), "r"(b1));
}
__device__ __forceinline__ void ldmx4(uint32_t* r, uint32_t addr)
{
    asm volatile("ldmatrix.sync.aligned.m8n8.x4.shared.b16 {%0,%1,%2,%3}, [%4];"
                 : "=r"(r[0]), "=r"(r[1]), "=r"(r[2]), "=r"(r[3]) : "r"(addr));
}
__device__ __forceinline__ unsigned h2pack(float lo, float hi) {
    __half2 h = __floats2half2_rn(lo, hi);
    return *reinterpret_cast<unsigned*>(&h);
}
__device__ __forceinline__ void cp_async16(uint32_t smem_u32, const void* gptr) {
    asm volatile("cp.async.cg.shared.global [%0], [%1], 16;" :: "r"(smem_u32), "l"(gptr));
}

// ---------------- mask dtype detection ----------------
__global__ void detect_mask_kernel(const unsigned* __restrict__ m) {
    if (threadIdx.x == 0) {
        bool is_i32 = true, is_f32 = true;
        for (int i = 0; i < 256; i++) {
            unsigned w = m[i];
            if (w > 1u) is_i32 = false;
            if (w != 0u && w != 0x3F800000u) is_f32 = false;
        }
        g_mask_mode = is_i32 ? 1 : (is_f32 ? 2 : 0);
    }
}

// ---------------- mask bit packing (transposed output) ----------------
__global__ void pack_mask_kernel(const void* __restrict__ mraw) {
    int gid = blockIdx.x * blockDim.x + threadIdx.x;
    if (gid >= (NN / 32) * NN) return;
    int r  = gid & (NN - 1);
    int wi = gid >> 12;
    int mode = g_mask_mode;
    size_t base = (size_t)r * NN + (size_t)wi * 32;
    unsigned bits = 0;
    if (mode == 1) {
        const int* p = (const int*)mraw;
        #pragma unroll
        for (int b = 0; b < 32; b++) bits |= (unsigned)(p[base + b] != 0) << b;
    } else if (mode == 2) {
        const float* p = (const float*)mraw;
        #pragma unroll
        for (int b = 0; b < 32; b++) bits |= (unsigned)(p[base + b] != 0.0f) << b;
    } else {
        const unsigned char* p = (const unsigned char*)mraw;
        #pragma unroll
        for (int b = 0; b < 32; b++) bits |= (unsigned)(p[base + b] != 0) << b;
    }
    g_maskbits[(size_t)wi * NN + r] = bits;
}

// ---------------- prep kernels ----------------
__global__ void convert_x_kernel(const float* __restrict__ x) {
    int gid = blockIdx.x * 256 + threadIdx.x;
    if (gid < NN * 128) g_xh[gid] = __float2half(x[gid]);
}
// W [K][N] fp32 -> Wt [N][K] fp16
__global__ void transposew_kernel(const float* __restrict__ W, __half* __restrict__ Wt,
                                  int K, int N) {
    int gid = blockIdx.x * 256 + threadIdx.x;
    if (gid >= K * N) return;
    int n = gid / K, k = gid - n * K;
    Wt[gid] = __float2half(W[(size_t)k * N + n]);
}

// ---------------- hgemm128: C[row][col] = sum_k A[row][k] B[col][k], K=128 ----------
#define HG_BUF   18432
#define HG_BOFF  36864
#define HG_SMEM  73728

__global__ __launch_bounds__(256, 2) void hgemm128_kernel(
    const __half* __restrict__ A, const __half* __restrict__ B,
    const float* __restrict__ bias, int bias_per_row, float scale,
    __half* __restrict__ C, int ldc)
{
    extern __shared__ unsigned char sm2[];

    const int tid  = threadIdx.x;
    const int lane = tid & 31;
    const int warp = tid >> 5;
    const int g    = lane >> 2;
    const int tig  = lane & 3;
    const int row0 = blockIdx.y * 128;
    const int col0 = blockIdx.x * 128;
    const int rg   = (warp & 3) * 32;
    const int dof  = (warp >> 2) * 64;

    const uint32_t smb = (uint32_t)__cvta_generic_to_shared(sm2);
    const char* ap = (const char*)(A + (size_t)row0 * 128);
    const char* bp = (const char*)(B + (size_t)col0 * 128);

    #pragma unroll
    for (int t = 0; t < 2; t++) {
        #pragma unroll
        for (int it = 0; it < 4; it++) {
            int idx = it * 256 + tid, r = idx >> 3, ch = idx & 7;
            cp_async16(smb + t * HG_BUF + r * 144 + ch * 16,
                       ap + (size_t)r * 256 + t * 128 + ch * 16);
            cp_async16(smb + HG_BOFF + t * HG_BUF + r * 144 + ch * 16,
                       bp + (size_t)r * 256 + t * 128 + ch * 16);
        }
        asm volatile("cp.async.commit_group;");
    }
    asm volatile("cp.async.wait_group 0;");
    __syncthreads();

    const int aquad   = lane >> 4;
    const int arow_in = lane & 15;
    const int bquad   = lane >> 3;
    const int brow_in = (lane & 7) + ((bquad >> 1) << 3);
    const int bkcol   = (bquad & 1) << 3;

    float o[2][8][4] = {};
    #pragma unroll
    for (int t = 0; t < 2; t++) {
        const uint32_t psb = smb + t * HG_BUF;
        const uint32_t vtb = smb + HG_BOFF + t * HG_BUF;
        #pragma unroll
        for (int kf = 0; kf < 4; kf++) {
            uint32_t a0r[4], a1r[4];
            ldmx4(a0r, psb + ((rg + arow_in) * 72 + kf * 16 + aquad * 8) * 2);
            ldmx4(a1r, psb + ((rg + 16 + arow_in) * 72 + kf * 16 + aquad * 8) * 2);
            #pragma unroll
            for (int nbp = 0; nbp < 4; nbp++) {
                uint32_t br[4];
                const int nrow = dof + nbp * 16 + brow_in;
                ldmx4(br, vtb + (nrow * 72 + kf * 16 + bkcol) * 2);
                mma_f16(o[0][2 * nbp],     a0r, br[0], br[1]);
                mma_f16(o[0][2 * nbp + 1], a0r, br[2], br[3]);
                mma_f16(o[1][2 * nbp],     a1r, br[0], br[1]);
                mma_f16(o[1][2 * nbp + 1], a1r, br[2], br[3]);
            }
        }
    }

    #pragma unroll
    for (int f = 0; f < 2; f++) {
        const int lr1 = row0 + rg + f * 16 + g, lr2 = lr1 + 8;
        #pragma unroll
        for (int nb = 0; nb < 8; nb++) {
            const int c = col0 + dof + nb * 8 + 2 * tig;
            float b00, b01, b10, b11;
            if (bias_per_row) { b00 = b01 = bias[lr1]; b10 = b11 = bias[lr2]; }
            else              { b00 = b10 = bias[c];  b01 = b11 = bias[c + 1]; }
            *(unsigned*)(C + (size_t)lr1 * ldc + c) =
                h2pack((o[f][nb][0] + b00) * scale, (o[f][nb][1] + b01) * scale);
            *(unsigned*)(C + (size_t)lr2 * ldc + c) =
                h2pack((o[f][nb][2] + b10) * scale, (o[f][nb][3] + b11) * scale);
        }
    }
}

// ---------------- fused attention, FA2-style register-resident P ----------------
// CTA = 128 rows x 1 head, 8 warps. Warp owns 16 rows x full 128 dm.
// Per 64-key tile (two 32-key halves): S mma -> exp -> h2pack = PV A-fragments
// directly (C-fragment of S == A-fragment layout after packing). No P smem,
// no phase remap, 1 barrier/tile. smem: KT 2x5120 | VT 2x18432 = 47104.
#define F_KT    0
#define F_VT    10240
#define F_SMEM  47104

__global__ __launch_bounds__(256, 2) void attn_fused_kernel(const float* __restrict__ ebias)
{
    extern __shared__ unsigned char smf[];

    const int tid  = threadIdx.x;
    const int lane = tid & 31;
    const int warp = tid >> 5;
    const int g    = lane >> 2;
    const int tig  = lane & 3;
    const int head = blockIdx.y;
    const int row0 = blockIdx.x * 128;
    const int r1   = row0 + warp * 16 + g;
    const int r2   = r1 + 8;
    const float ESH = 4.1588830833596715f;   // 6*ln2

    const int skey = tid >> 2;
    const int sseg = tid & 3;

    const uint32_t smb = (uint32_t)__cvta_generic_to_shared(smf);
    __half* KT = (__half*)(smf + F_KT);

    const int bquad   = lane >> 3;
    const int brow_in = (lane & 7) + ((bquad >> 1) << 3);
    const int bkcol   = (bquad & 1) << 3;

    // Q fragments: direct fp16 loads (scale folded in projection)
    uint32_t qa[2][4];
    {
        const __half* q1 = g_qh + (size_t)r1 * 256 + head * 32;
        const __half* q2 = g_qh + (size_t)r2 * 256 + head * 32;
        #pragma unroll
        for (int ks = 0; ks < 2; ks++) {
            const int k0 = ks * 16 + 2 * tig;
            qa[ks][0] = *(const uint32_t*)(q1 + k0);
            qa[ks][1] = *(const uint32_t*)(q2 + k0);
            qa[ks][2] = *(const uint32_t*)(q1 + k0 + 8);
            qa[ks][3] = *(const uint32_t*)(q2 + k0 + 8);
        }
    }

    float o[16][4] = {};
    float la1 = 0.f, la2 = 0.f;

    const char* vv0 = (const char*)(g_vt + (size_t)(head * 128) * NN);

    #define FVT_ISSUE(t, buf) do {                                               \
        _Pragma("unroll")                                                        \
        for (int it = 0; it < 4; it++) {                                         \
            int idx = it * 256 + tid, d = idx >> 3, ch = idx & 7;                \
            cp_async16(smb + F_VT + (buf) * 18432 + d * 144 + ch * 16,           \
                       vv0 + (size_t)d * (NN * 2) + (size_t)(t) * 128 + ch * 16);\
        }                                                                        \
        asm volatile("cp.async.commit_group;");                                  \
    } while (0)

    // prologue: KT(0) + VT(0)
    {
        *(uint4*)&KT[skey * 40 + sseg * 8] =
            *(const uint4*)(g_kh + (size_t)skey * 256 + head * 32 + sseg * 8);
        FVT_ISSUE(0, 0);
    }
    asm volatile("cp.async.wait_group 0;");
    __syncthreads();

    for (int t = 0; t < NN / 64; ++t) {
        const int cur = t & 1;
        const bool pf = (t + 1 < NN / 64);

        uint4 pk;
        if (pf) {
            FVT_ISSUE(t + 1, cur ^ 1);
            pk = *(const uint4*)(g_kh + (size_t)((t + 1) * 64 + skey) * 256
                                 + head * 32 + sseg * 8);
        }

        const uint32_t ktc = smb + F_KT + cur * 5120;
        const uint32_t vtb = smb + F_VT + cur * 18432;

        #pragma unroll
        for (int h = 0; h < 2; ++h) {
            // ---- S for 32 keys ----
            float s[4][4];
            #pragma unroll
            for (int nb = 0; nb < 4; nb++) { s[nb][0] = s[nb][1] = s[nb][2] = s[nb][3] = 0.f; }
            #pragma unroll
            for (int ks = 0; ks < 2; ks++) {
                #pragma unroll
                for (int j = 0; j < 2; j++) {
                    uint32_t br[4];
                    const int krow = (2 * h + j) * 16 + brow_in;
                    ldmx4(br, ktc + (krow * 40 + ks * 16 + bkcol) * 2);
                    mma_f16(s[2 * j],     qa[ks], br[0], br[1]);
                    mma_f16(s[2 * j + 1], qa[ks], br[2], br[3]);
                }
            }
            const int col0 = t * 64 + h * 32;
            if (head == 0) {
                #pragma unroll
                for (int nb = 0; nb < 4; nb++) {
                    float2 b01 = *(const float2*)(ebias + (size_t)r1 * NN + col0 + nb * 8 + 2 * tig);
                    float2 b23 = *(const float2*)(ebias + (size_t)r2 * NN + col0 + nb * 8 + 2 * tig);
                    s[nb][0] += b01.x; s[nb][1] += b01.y;
                    s[nb][2] += b23.x; s[nb][3] += b23.y;
                }
            }
            {
                const unsigned w1 = g_maskbits[(size_t)(2 * t + h) * NN + r1];
                const unsigned w2 = g_maskbits[(size_t)(2 * t + h) * NN + r2];
                #pragma unroll
                for (int nb = 0; nb < 4; nb++) {
                    const int c = nb * 8 + 2 * tig;
                    if ((w1 >> c) & 1u)       s[nb][0] = -1e9f;
                    if ((w1 >> (c + 1)) & 1u) s[nb][1] = -1e9f;
                    if ((w2 >> c) & 1u)       s[nb][2] = -1e9f;
                    if ((w2 >> (c + 1)) & 1u) s[nb][3] = -1e9f;
                }
            }

            // ---- exp -> fp16 packs; these ARE the PV A-fragments ----
            uint32_t u1[4], u2[4];
            #pragma unroll
            for (int nb = 0; nb < 4; nb++) {
                float p0 = __expf(s[nb][0] - ESH);
                float p1 = __expf(s[nb][1] - ESH);
                float p2 = __expf(s[nb][2] - ESH);
                float p3 = __expf(s[nb][3] - ESH);
                u1[nb] = h2pack(p0, p1);
                u2[nb] = h2pack(p2, p3);
                __half2 h1 = *reinterpret_cast<__half2*>(&u1[nb]);
                __half2 h2v = *reinterpret_cast<__half2*>(&u2[nb]);
                float2 f1 = __half22float2(h1);
                float2 f2 = __half22float2(h2v);
                la1 += f1.x + f1.y;
                la2 += f2.x + f2.y;
            }

            // ---- PV for these 32 keys: 2 x (16-key kstep) over full 128 dm ----
            #pragma unroll
            for (int kb = 0; kb < 2; kb++) {
                uint32_t af[4];
                af[0] = u1[2 * kb];      // rows g,   keys 16kb + 2tig,+1
                af[1] = u2[2 * kb];      // rows g+8
                af[2] = u1[2 * kb + 1];  // rows g,   keys +8
                af[3] = u2[2 * kb + 1];  // rows g+8
                const int kof = h * 32 + kb * 16 + bkcol;
                #pragma unroll
                for (int nbp = 0; nbp < 8; nbp++) {
                    uint32_t br[4];
                    ldmx4(br, vtb + ((nbp * 16 + brow_in) * 72 + kof) * 2);
                    mma_f16(o[2 * nbp],     af, br[0], br[1]);
                    mma_f16(o[2 * nbp + 1], af, br[2], br[3]);
                }
            }
        }

        // stage next K tile; drain VT(t+1) copy; flip buffers
        if (pf) {
            *(uint4*)&KT[(cur ^ 1) * 2560 + skey * 40 + sseg * 8] = pk;
            asm volatile("cp.async.wait_group 0;");
        }
        __syncthreads();
    }

    // ---- finalize: l is warp-local; divide and store fp16 ----
    la1 += __shfl_xor_sync(0xffffffffu, la1, 1);
    la1 += __shfl_xor_sync(0xffffffffu, la1, 2);
    la2 += __shfl_xor_sync(0xffffffffu, la2, 1);
    la2 += __shfl_xor_sync(0xffffffffu, la2, 2);
    const float i1 = 1.f / la1;
    const float i2 = 1.f / la2;
    __half* p1 = g_attnh + (size_t)r1 * 1024 + head * 128;
    __half* p2 = g_attnh + (size_t)r2 * 1024 + head * 128;
    #pragma unroll
    for (int nb = 0; nb < 16; nb++) {
        const int c = nb * 8 + 2 * tig;
        *(unsigned*)(p1 + c) = h2pack(o[nb][0] * i1, o[nb][1] * i1);
        *(unsigned*)(p2 + c) = h2pack(o[nb][2] * i2, o[nb][3] * i2);
    }
}

// ---------------- out projection: out = attnh @ Wo + bo (fp16 mma, K=1024) --------
#define P2_BUF   18432
#define P2_VTOFF 36864
#define P2_SMEM  73728

__global__ __launch_bounds__(256, 2) void outproj_kernel(const float* __restrict__ bo,
                                                         float* __restrict__ out)
{
    extern __shared__ unsigned char sm2[];

    const int tid  = threadIdx.x;
    const int lane = tid & 31;
    const int warp = tid >> 5;
    const int g    = lane >> 2;
    const int tig  = lane & 3;
    const int row0 = blockIdx.x * 128;
    const int rg   = (warp & 3) * 32;
    const int dof  = (warp >> 2) * 64;

    const uint32_t smb = (uint32_t)__cvta_generic_to_shared(sm2);
    const char* ap = (const char*)g_attnh + (size_t)row0 * 2048;
    const char* bp = (const char*)g_wot;

    const int aquad   = lane >> 4;
    const int arow_in = lane & 15;
    const int bquad   = lane >> 3;
    const int brow_in = (lane & 7) + ((bquad >> 1) << 3);
    const int bkcol   = (bquad & 1) << 3;

    float o[2][8][4] = {};

    #define OISSUE(t, buf) do {                                                  \
        _Pragma("unroll")                                                        \
        for (int it = 0; it < 4; it++) {                                         \
            int idx = it * 256 + tid, r = idx >> 3, ch = idx & 7;                \
            cp_async16(smb + (buf) * P2_BUF + r * 144 + ch * 16,                 \
                       ap + (size_t)r * 2048 + (t) * 128 + ch * 16);             \
            cp_async16(smb + P2_VTOFF + (buf) * P2_BUF + r * 144 + ch * 16,      \
                       bp + (size_t)r * 2048 + (t) * 128 + ch * 16);             \
        }                                                                        \
        asm volatile("cp.async.commit_group;");                                  \
    } while (0)

    OISSUE(0, 0);

    for (int t = 0; t < 16; ++t) {
        const int cur = t & 1;
        if (t + 1 < 16) {
            OISSUE(t + 1, cur ^ 1);
            asm volatile("cp.async.wait_group 1;");
        } else {
            asm volatile("cp.async.wait_group 0;");
        }
        __syncthreads();

        const uint32_t psb = smb + cur * P2_BUF;
        const uint32_t vtb = smb + P2_VTOFF + cur * P2_BUF;
        #pragma unroll
        for (int kf = 0; kf < 4; kf++) {
            uint32_t a0r[4], a1r[4];
            ldmx4(a0r, psb + ((rg + arow_in) * 72 + kf * 16 + aquad * 8) * 2);
            ldmx4(a1r, psb + ((rg + 16 + arow_in) * 72 + kf * 16 + aquad * 8) * 2);
            #pragma unroll
            for (int nbp = 0; nbp < 4; nbp++) {
                uint32_t br[4];
                const int nrow = dof + nbp * 16 + brow_in;
                ldmx4(br, vtb + (nrow * 72 + kf * 16 + bkcol) * 2);
                mma_f16(o[0][2 * nbp],     a0r, br[0], br[1]);
                mma_f16(o[0][2 * nbp + 1], a0r, br[2], br[3]);
                mma_f16(o[1][2 * nbp],     a1r, br[0], br[1]);
                mma_f16(o[1][2 * nbp + 1], a1r, br[2], br[3]);
            }
        }
        __syncthreads();
    }

    #pragma unroll
    for (int f = 0; f < 2; f++) {
        const int lr1 = rg + f * 16 + g, lr2 = lr1 + 8;
        #pragma unroll
        for (int nb = 0; nb < 8; nb++) {
            const int c = dof + nb * 8 + 2 * tig;
            const float b0 = bo[c], b1 = bo[c + 1];
            float2 va; va.x = o[f][nb][0] + b0; va.y = o[f][nb][1] + b1;
            float2 vb; vb.x = o[f][nb][2] + b0; vb.y = o[f][nb][3] + b1;
            *(float2*)(out + (size_t)(row0 + lr1) * 128 + c) = va;
            *(float2*)(out + (size_t)(row0 + lr2) * 128 + c) = vb;
        }
    }
}

// ---------------- launch ----------------
extern "C" void kernel_launch(void* const* d_in, const int* in_sizes, int n_in,
                              void* d_out, int out_size)
{
    const float* x     = (const float*)d_in[0];
    const void*  mask  = (const void*) d_in[1];
    const float* ebias = (const float*)d_in[2];
    const float* Wq    = (const float*)d_in[3];
    const float* bq    = (const float*)d_in[4];
    const float* Wk    = (const float*)d_in[5];
    const float* bk    = (const float*)d_in[6];
    const float* Wv    = (const float*)d_in[7];
    const float* bv    = (const float*)d_in[8];
    const float* Wo    = (const float*)d_in[9];
    const float* bo    = (const float*)d_in[10];
    float* out = (float*)d_out;

    __half *xh, *qh, *kh, *vt, *wqt, *wkt, *wvt, *wot;
    cudaGetSymbolAddress((void**)&xh,  g_xh);
    cudaGetSymbolAddress((void**)&qh,  g_qh);
    cudaGetSymbolAddress((void**)&kh,  g_kh);
    cudaGetSymbolAddress((void**)&vt,  g_vt);
    cudaGetSymbolAddress((void**)&wqt, g_wqt);
    cudaGetSymbolAddress((void**)&wkt, g_wkt);
    cudaGetSymbolAddress((void**)&wvt, g_wvt);
    cudaGetSymbolAddress((void**)&wot, g_wot);

    static bool attr_done = false;
    if (!attr_done) {
        cudaFuncSetAttribute(attn_fused_kernel, cudaFuncAttributeMaxDynamicSharedMemorySize,
                             F_SMEM);
        cudaFuncSetAttribute(outproj_kernel, cudaFuncAttributeMaxDynamicSharedMemorySize,
                             P2_SMEM);
        cudaFuncSetAttribute(hgemm128_kernel, cudaFuncAttributeMaxDynamicSharedMemorySize,
                             HG_SMEM);
        attr_done = true;
    }

    detect_mask_kernel<<<1, 32>>>((const unsigned*)mask);
    pack_mask_kernel<<<((NN / 32) * NN + 255) / 256, 256>>>(mask);

    convert_x_kernel<<<(NN * 128 + 255) / 256, 256>>>(x);
    transposew_kernel<<<(128 * 256 + 255) / 256, 256>>>(Wq, wqt, 128, 256);
    transposew_kernel<<<(128 * 256 + 255) / 256, 256>>>(Wk, wkt, 128, 256);
    transposew_kernel<<<(128 * 1024 + 255) / 256, 256>>>(Wv, wvt, 128, 1024);
    transposew_kernel<<<(1024 * 128 + 255) / 256, 256>>>(Wo, wot, 1024, 128);

    hgemm128_kernel<<<dim3(2, 32), 256, HG_SMEM>>>(xh, wqt, bq, 0, 0.17677669529663687f,
                                                   qh, 256);
    hgemm128_kernel<<<dim3(2, 32), 256, HG_SMEM>>>(xh, wkt, bk, 0, 1.0f, kh, 256);
    hgemm128_kernel<<<dim3(32, 8), 256, HG_SMEM>>>(wvt, xh, bv, 1, 1.0f, vt, NN);

    attn_fused_kernel<<<dim3(NN / 128, HEADS), 256, F_SMEM>>>(ebias);

    outproj_kernel<<<NN / 128, 256, P2_SMEM>>>(bo, out);
}

// round 16
// speedup vs baseline: 1.0789x; 1.0789x over previous
#include <cuda_runtime.h>
#include <cuda_bf16.h>
#include <cuda_fp16.h>
#include <cstdint>

#define NN     4096
#define DM     128
#define QK     32
#define HEADS  8

// ---------------- device scratch (no allocation allowed) ----------------
__device__ static __half         g_xh[NN * 128];                  // x fp16
__device__ static __half         g_qh[NN * 256];                  // Q*qs fp16 [node][h*32+d]
__device__ static __half         g_kh[NN * 256];                  // K fp16
__device__ static __half         g_vt[(size_t)1024 * NN];         // [h*128+d][node], fp16
__device__ static __half         g_attnh[(size_t)NN * 1024];      // attention out, fp16
__device__ static __half         g_wqt[256 * 128];                // W^T fp16 [out][in]
__device__ static __half         g_wkt[256 * 128];
__device__ static __half         g_wvt[1024 * 128];
__device__ static __half         g_wot[128 * 1024];
__device__ static unsigned       g_maskbits[(NN / 32) * NN];      // [wordIdx][row]

// ---------------- helpers ----------------
__device__ __forceinline__ void mma_f16(float* d, const uint32_t* a, uint32_t b0, uint32_t b1)
{
    asm volatile("mma.sync.aligned.m16n8k16.row.col.f32.f16.f16.f32 "
                 "{%0,%1,%2,%3}, {%4,%5,%6,%7}, {%8,%9}, {%0,%1,%2,%3};"
                 : "+f"(d[0]), "+f"(d[1]), "+f"(d[2]), "+f"(d[3])
                 : "r"(a[0]), "r"(a[1]), "r"(a[2]), "r"(a[3]), "r"(b0), "r"(b1));
}
__device__ __forceinline__ void ldmx4(uint32_t* r, uint32_t addr)
{
    asm volatile("ldmatrix.sync.aligned.m8n8.x4.shared.b16 {%0,%1,%2,%3}, [%4];"
                 : "=r"(r[0]), "=r"(r[1]), "=r"(r[2]), "=r"(r[3]) : "r"(addr));
}
__device__ __forceinline__ unsigned h2pack(float lo, float hi) {
    __half2 h = __floats2half2_rn(lo, hi);
    return *reinterpret_cast<unsigned*>(&h);
}
__device__ __forceinline__ void cp_async16(uint32_t smem_u32, const void* gptr) {
    asm volatile("cp.async.cg.shared.global [%0], [%1], 16;" :: "r"(smem_u32), "l"(gptr));
}

// ---------------- mask pack with inline dtype detection ----------------
__global__ void pack_mask_kernel(const void* __restrict__ mraw) {
    __shared__ int smode;
    if (threadIdx.x == 0) {
        const unsigned* m = (const unsigned*)mraw;
        bool is_i32 = true, is_f32 = true;
        for (int i = 0; i < 256; i++) {
            unsigned w = m[i];
            if (w > 1u) is_i32 = false;
            if (w != 0u && w != 0x3F800000u) is_f32 = false;
        }
        smode = is_i32 ? 1 : (is_f32 ? 2 : 0);
    }
    __syncthreads();
    const int mode = smode;

    int gid = blockIdx.x * blockDim.x + threadIdx.x;
    if (gid >= (NN / 32) * NN) return;
    int r  = gid & (NN - 1);
    int wi = gid >> 12;
    size_t base = (size_t)r * NN + (size_t)wi * 32;
    unsigned bits = 0;
    if (mode == 1) {
        const int* p = (const int*)mraw;
        #pragma unroll
        for (int b = 0; b < 32; b++) bits |= (unsigned)(p[base + b] != 0) << b;
    } else if (mode == 2) {
        const float* p = (const float*)mraw;
        #pragma unroll
        for (int b = 0; b < 32; b++) bits |= (unsigned)(p[base + b] != 0.0f) << b;
    } else {
        const unsigned char* p = (const unsigned char*)mraw;
        #pragma unroll
        for (int b = 0; b < 32; b++) bits |= (unsigned)(p[base + b] != 0) << b;
    }
    g_maskbits[(size_t)wi * NN + r] = bits;
}

// ---------------- merged prep: x->fp16 + 4 weight transposes ----------------
// blocks [0,2048): convert_x | [2048,2176): Wq^T | [2176,2304): Wk^T
// [2304,2816): Wv^T | [2816,3328): Wo^T
__global__ void prep_all_kernel(const float* __restrict__ x,
                                const float* __restrict__ Wq, const float* __restrict__ Wk,
                                const float* __restrict__ Wv, const float* __restrict__ Wo)
{
    const int b = blockIdx.x;
    if (b < 2048) {
        int gid = b * 256 + threadIdx.x;
        g_xh[gid] = __float2half(x[gid]);
        return;
    }
    const float* W; __half* Wt; int K, N, lb;
    if (b < 2176)      { W = Wq; Wt = g_wqt; K = 128;  N = 256;  lb = b - 2048; }
    else if (b < 2304) { W = Wk; Wt = g_wkt; K = 128;  N = 256;  lb = b - 2176; }
    else if (b < 2816) { W = Wv; Wt = g_wvt; K = 128;  N = 1024; lb = b - 2304; }
    else               { W = Wo; Wt = g_wot; K = 1024; N = 128;  lb = b - 2816; }
    int gid = lb * 256 + threadIdx.x;
    if (gid >= K * N) return;
    int n = gid / K, k = gid - n * K;
    Wt[gid] = __float2half(W[(size_t)k * N + n]);
}

// ---------------- hgemm128: C[row][col] = sum_k A[row][k] B[col][k], K=128 ----------
#define HG_BUF   18432
#define HG_BOFF  36864
#define HG_SMEM  73728

__global__ __launch_bounds__(256, 2) void hgemm128_kernel(
    const __half* __restrict__ A, const __half* __restrict__ B,
    const float* __restrict__ bias, int bias_per_row, float scale,
    __half* __restrict__ C, int ldc)
{
    extern __shared__ unsigned char sm2[];

    const int tid  = threadIdx.x;
    const int lane = tid & 31;
    const int warp = tid >> 5;
    const int g    = lane >> 2;
    const int tig  = lane & 3;
    const int row0 = blockIdx.y * 128;
    const int col0 = blockIdx.x * 128;
    const int rg   = (warp & 3) * 32;
    const int dof  = (warp >> 2) * 64;

    const uint32_t smb = (uint32_t)__cvta_generic_to_shared(sm2);
    const char* ap = (const char*)(A + (size_t)row0 * 128);
    const char* bp = (const char*)(B + (size_t)col0 * 128);

    #pragma unroll
    for (int t = 0; t < 2; t++) {
        #pragma unroll
        for (int it = 0; it < 4; it++) {
            int idx = it * 256 + tid, r = idx >> 3, ch = idx & 7;
            cp_async16(smb + t * HG_BUF + r * 144 + ch * 16,
                       ap + (size_t)r * 256 + t * 128 + ch * 16);
            cp_async16(smb + HG_BOFF + t * HG_BUF + r * 144 + ch * 16,
                       bp + (size_t)r * 256 + t * 128 + ch * 16);
        }
        asm volatile("cp.async.commit_group;");
    }
    asm volatile("cp.async.wait_group 0;");
    __syncthreads();

    const int aquad   = lane >> 4;
    const int arow_in = lane & 15;
    const int bquad   = lane >> 3;
    const int brow_in = (lane & 7) + ((bquad >> 1) << 3);
    const int bkcol   = (bquad & 1) << 3;

    float o[2][8][4] = {};
    #pragma unroll
    for (int t = 0; t < 2; t++) {
        const uint32_t psb = smb + t * HG_BUF;
        const uint32_t vtb = smb + HG_BOFF + t * HG_BUF;
        #pragma unroll
        for (int kf = 0; kf < 4; kf++) {
            uint32_t a0r[4], a1r[4];
            ldmx4(a0r, psb + ((rg + arow_in) * 72 + kf * 16 + aquad * 8) * 2);
            ldmx4(a1r, psb + ((rg + 16 + arow_in) * 72 + kf * 16 + aquad * 8) * 2);
            #pragma unroll
            for (int nbp = 0; nbp < 4; nbp++) {
                uint32_t br[4];
                const int nrow = dof + nbp * 16 + brow_in;
                ldmx4(br, vtb + (nrow * 72 + kf * 16 + bkcol) * 2);
                mma_f16(o[0][2 * nbp],     a0r, br[0], br[1]);
                mma_f16(o[0][2 * nbp + 1], a0r, br[2], br[3]);
                mma_f16(o[1][2 * nbp],     a1r, br[0], br[1]);
                mma_f16(o[1][2 * nbp + 1], a1r, br[2], br[3]);
            }
        }
    }

    #pragma unroll
    for (int f = 0; f < 2; f++) {
        const int lr1 = row0 + rg + f * 16 + g, lr2 = lr1 + 8;
        #pragma unroll
        for (int nb = 0; nb < 8; nb++) {
            const int c = col0 + dof + nb * 8 + 2 * tig;
            float b00, b01, b10, b11;
            if (bias_per_row) { b00 = b01 = bias[lr1]; b10 = b11 = bias[lr2]; }
            else              { b00 = b10 = bias[c];  b01 = b11 = bias[c + 1]; }
            *(unsigned*)(C + (size_t)lr1 * ldc + c) =
                h2pack((o[f][nb][0] + b00) * scale, (o[f][nb][1] + b01) * scale);
            *(unsigned*)(C + (size_t)lr2 * ldc + c) =
                h2pack((o[f][nb][2] + b10) * scale, (o[f][nb][3] + b11) * scale);
        }
    }
}

// ---------------- fused attention (R14 two-phase, best known) ----------------
#define F_KT    0
#define F_VT    10240
#define F_PS    47104
#define F_LR    65536
#define F_SMEM  66048

__global__ __launch_bounds__(256, 2) void attn_fused_kernel(const float* __restrict__ ebias)
{
    extern __shared__ unsigned char smf[];

    const int tid  = threadIdx.x;
    const int lane = tid & 31;
    const int warp = tid >> 5;
    const int g    = lane >> 2;
    const int tig  = lane & 3;
    const int head = blockIdx.y;
    const int row0 = blockIdx.x * 128;
    const int r1   = row0 + warp * 16 + g;
    const int r2   = r1 + 8;
    const int rg   = (warp & 3) * 32;
    const int dof  = (warp >> 2) * 64;
    const float ESH = 4.1588830833596715f;   // 6*ln2

    const int skey = tid >> 2;
    const int sseg = tid & 3;

    const uint32_t smb = (uint32_t)__cvta_generic_to_shared(smf);
    __half* KT = (__half*)(smf + F_KT);
    __half* PS = (__half*)(smf + F_PS);
    float*  LR = (float*)(smf + F_LR);

    const int aquad   = lane >> 4;
    const int arow_in = lane & 15;
    const int bquad   = lane >> 3;
    const int brow_in = (lane & 7) + ((bquad >> 1) << 3);
    const int bkcol   = (bquad & 1) << 3;

    uint32_t qa[2][4];
    {
        const __half* q1 = g_qh + (size_t)r1 * 256 + head * 32;
        const __half* q2 = g_qh + (size_t)r2 * 256 + head * 32;
        #pragma unroll
        for (int ks = 0; ks < 2; ks++) {
            const int k0 = ks * 16 + 2 * tig;
            qa[ks][0] = *(const uint32_t*)(q1 + k0);
            qa[ks][1] = *(const uint32_t*)(q2 + k0);
            qa[ks][2] = *(const uint32_t*)(q1 + k0 + 8);
            qa[ks][3] = *(const uint32_t*)(q2 + k0 + 8);
        }
    }

    float o[2][8][4] = {};
    float la1 = 0.f, la2 = 0.f;

    const char* vv0 = (const char*)(g_vt + (size_t)(head * 128) * NN);

    #define FVT_ISSUE(t, buf) do {                                               \
        _Pragma("unroll")                                                        \
        for (int it = 0; it < 4; it++) {                                         \
            int idx = it * 256 + tid, d = idx >> 3, ch = idx & 7;                \
            cp_async16(smb + F_VT + (buf) * 18432 + d * 144 + ch * 16,           \
                       vv0 + (size_t)d * (NN * 2) + (size_t)(t) * 128 + ch * 16);\
        }                                                                        \
        asm volatile("cp.async.commit_group;");                                  \
    } while (0)

    {
        *(uint4*)&KT[skey * 40 + sseg * 8] =
            *(const uint4*)(g_kh + (size_t)skey * 256 + head * 32 + sseg * 8);
        FVT_ISSUE(0, 0);
    }
    __syncthreads();

    for (int t = 0; t < NN / 64; ++t) {
        const int cur = t & 1;
        const bool pf = (t + 1 < NN / 64);

        uint4 pk;
        if (pf) {
            FVT_ISSUE(t + 1, cur ^ 1);
            pk = *(const uint4*)(g_kh + (size_t)((t + 1) * 64 + skey) * 256
                                 + head * 32 + sseg * 8);
        }

        // ---- phase A: S -> exp -> PS (two 32-key halves) ----
        const uint32_t ktc = smb + F_KT + cur * 5120;
        #pragma unroll
        for (int h = 0; h < 2; ++h) {
            float s[4][4];
            #pragma unroll
            for (int nb = 0; nb < 4; nb++) { s[nb][0] = s[nb][1] = s[nb][2] = s[nb][3] = 0.f; }
            #pragma unroll
            for (int ks = 0; ks < 2; ks++) {
                #pragma unroll
                for (int j = 0; j < 2; j++) {
                    uint32_t br[4];
                    const int krow = (2 * h + j) * 16 + brow_in;
                    ldmx4(br, ktc + (krow * 40 + ks * 16 + bkcol) * 2);
                    mma_f16(s[2 * j],     qa[ks], br[0], br[1]);
                    mma_f16(s[2 * j + 1], qa[ks], br[2], br[3]);
                }
            }
            const int col0 = t * 64 + h * 32;
            if (head == 0) {
                #pragma unroll
                for (int nb = 0; nb < 4; nb++) {
                    float2 b01 = *(const float2*)(ebias + (size_t)r1 * NN + col0 + nb * 8 + 2 * tig);
                    float2 b23 = *(const float2*)(ebias + (size_t)r2 * NN + col0 + nb * 8 + 2 * tig);
                    s[nb][0] += b01.x; s[nb][1] += b01.y;
                    s[nb][2] += b23.x; s[nb][3] += b23.y;
                }
            }
            {
                const unsigned w1 = g_maskbits[(size_t)(2 * t + h) * NN + r1];
                const unsigned w2 = g_maskbits[(size_t)(2 * t + h) * NN + r2];
                #pragma unroll
                for (int nb = 0; nb < 4; nb++) {
                    const int c = nb * 8 + 2 * tig;
                    if ((w1 >> c) & 1u)       s[nb][0] = -1e9f;
                    if ((w1 >> (c + 1)) & 1u) s[nb][1] = -1e9f;
                    if ((w2 >> c) & 1u)       s[nb][2] = -1e9f;
                    if ((w2 >> (c + 1)) & 1u) s[nb][3] = -1e9f;
                }
            }
            #pragma unroll
            for (int nb = 0; nb < 4; nb++) {
                float p0 = __expf(s[nb][0] - ESH);
                float p1 = __expf(s[nb][1] - ESH);
                float p2 = __expf(s[nb][2] - ESH);
                float p3 = __expf(s[nb][3] - ESH);
                unsigned u1 = h2pack(p0, p1);
                unsigned u2 = h2pack(p2, p3);
                __half2 h1 = *reinterpret_cast<__half2*>(&u1);
                __half2 h2v = *reinterpret_cast<__half2*>(&u2);
                float2 f1 = __half22float2(h1);
                float2 f2 = __half22float2(h2v);
                la1 += f1.x + f1.y;
                la2 += f2.x + f2.y;
                const int c = h * 32 + nb * 8 + 2 * tig;
                *(unsigned*)(PS + (warp * 16 + g) * 72 + c)     = u1;
                *(unsigned*)(PS + (warp * 16 + g + 8) * 72 + c) = u2;
            }
        }

        if (pf) asm volatile("cp.async.wait_group 1;");
        else    asm volatile("cp.async.wait_group 0;");
        __syncthreads();

        // ---- phase B: O += P V ----
        {
            const uint32_t psb = smb + F_PS;
            const uint32_t vtb = smb + F_VT + cur * 18432;
            #pragma unroll
            for (int kf = 0; kf < 4; kf++) {
                uint32_t a0r[4], a1r[4];
                ldmx4(a0r, psb + ((rg + arow_in) * 72 + kf * 16 + aquad * 8) * 2);
                ldmx4(a1r, psb + ((rg + 16 + arow_in) * 72 + kf * 16 + aquad * 8) * 2);
                #pragma unroll
                for (int nbp = 0; nbp < 4; nbp++) {
                    uint32_t br[4];
                    const int nrow = dof + nbp * 16 + brow_in;
                    ldmx4(br, vtb + (nrow * 72 + kf * 16 + bkcol) * 2);
                    mma_f16(o[0][2 * nbp],     a0r, br[0], br[1]);
                    mma_f16(o[0][2 * nbp + 1], a0r, br[2], br[3]);
                    mma_f16(o[1][2 * nbp],     a1r, br[0], br[1]);
                    mma_f16(o[1][2 * nbp + 1], a1r, br[2], br[3]);
                }
            }
        }

        if (pf)
            *(uint4*)&KT[(cur ^ 1) * 2560 + skey * 40 + sseg * 8] = pk;
        __syncthreads();
    }

    la1 += __shfl_xor_sync(0xffffffffu, la1, 1);
    la1 += __shfl_xor_sync(0xffffffffu, la1, 2);
    la2 += __shfl_xor_sync(0xffffffffu, la2, 1);
    la2 += __shfl_xor_sync(0xffffffffu, la2, 2);
    if (tig == 0) {
        LR[warp * 16 + g]     = la1;
        LR[warp * 16 + g + 8] = la2;
    }
    __syncthreads();

    #pragma unroll
    for (int f = 0; f < 2; f++) {
        const int lr1 = rg + f * 16 + g;
        const int lr2 = lr1 + 8;
        const float i1 = 1.f / LR[lr1];
        const float i2 = 1.f / LR[lr2];
        __half* p1 = g_attnh + (size_t)(row0 + lr1) * 1024 + head * 128 + dof;
        __half* p2 = g_attnh + (size_t)(row0 + lr2) * 1024 + head * 128 + dof;
        #pragma unroll
        for (int nb = 0; nb < 8; nb++) {
            const int c = nb * 8 + 2 * tig;
            *(unsigned*)(p1 + c) = h2pack(o[f][nb][0] * i1, o[f][nb][1] * i1);
            *(unsigned*)(p2 + c) = h2pack(o[f][nb][2] * i2, o[f][nb][3] * i2);
        }
    }
}

// ---------------- out projection: out = attnh @ Wo + bo (fp16 mma, K=1024) --------
#define P2_BUF   18432
#define P2_VTOFF 36864
#define P2_SMEM  73728

__global__ __launch_bounds__(256, 2) void outproj_kernel(const float* __restrict__ bo,
                                                         float* __restrict__ out)
{
    extern __shared__ unsigned char sm2[];

    const int tid  = threadIdx.x;
    const int lane = tid & 31;
    const int warp = tid >> 5;
    const int g    = lane >> 2;
    const int tig  = lane & 3;
    const int row0 = blockIdx.x * 128;
    const int rg   = (warp & 3) * 32;
    const int dof  = (warp >> 2) * 64;

    const uint32_t smb = (uint32_t)__cvta_generic_to_shared(sm2);
    const char* ap = (const char*)g_attnh + (size_t)row0 * 2048;
    const char* bp = (const char*)g_wot;

    const int aquad   = lane >> 4;
    const int arow_in = lane & 15;
    const int bquad   = lane >> 3;
    const int brow_in = (lane & 7) + ((bquad >> 1) << 3);
    const int bkcol   = (bquad & 1) << 3;

    float o[2][8][4] = {};

    #define OISSUE(t, buf) do {                                                  \
        _Pragma("unroll")                                                        \
        for (int it = 0; it < 4; it++) {                                         \
            int idx = it * 256 + tid, r = idx >> 3, ch = idx & 7;                \
            cp_async16(smb + (buf) * P2_BUF + r * 144 + ch * 16,                 \
                       ap + (size_t)r * 2048 + (t) * 128 + ch * 16);             \
            cp_async16(smb + P2_VTOFF + (buf) * P2_BUF + r * 144 + ch * 16,      \
                       bp + (size_t)r * 2048 + (t) * 128 + ch * 16);             \
        }                                                                        \
        asm volatile("cp.async.commit_group;");                                  \
    } while (0)

    OISSUE(0, 0);

    for (int t = 0; t < 16; ++t) {
        const int cur = t & 1;
        if (t + 1 < 16) {
            OISSUE(t + 1, cur ^ 1);
            asm volatile("cp.async.wait_group 1;");
        } else {
            asm volatile("cp.async.wait_group 0;");
        }
        __syncthreads();

        const uint32_t psb = smb + cur * P2_BUF;
        const uint32_t vtb = smb + P2_VTOFF + cur * P2_BUF;
        #pragma unroll
        for (int kf = 0; kf < 4; kf++) {
            uint32_t a0r[4], a1r[4];
            ldmx4(a0r, psb + ((rg + arow_in) * 72 + kf * 16 + aquad * 8) * 2);
            ldmx4(a1r, psb + ((rg + 16 + arow_in) * 72 + kf * 16 + aquad * 8) * 2);
            #pragma unroll
            for (int nbp = 0; nbp < 4; nbp++) {
                uint32_t br[4];
                const int nrow = dof + nbp * 16 + brow_in;
                ldmx4(br, vtb + (nrow * 72 + kf * 16 + bkcol) * 2);
                mma_f16(o[0][2 * nbp],     a0r, br[0], br[1]);
                mma_f16(o[0][2 * nbp + 1], a0r, br[2], br[3]);
                mma_f16(o[1][2 * nbp],     a1r, br[0], br[1]);
                mma_f16(o[1][2 * nbp + 1], a1r, br[2], br[3]);
            }
        }
        __syncthreads();
    }

    #pragma unroll
    for (int f = 0; f < 2; f++) {
        const int lr1 = rg + f * 16 + g, lr2 = lr1 + 8;
        #pragma unroll
        for (int nb = 0; nb < 8; nb++) {
            const int c = dof + nb * 8 + 2 * tig;
            const float b0 = bo[c], b1 = bo[c + 1];
            float2 va; va.x = o[f][nb][0] + b0; va.y = o[f][nb][1] + b1;
            float2 vb; vb.x = o[f][nb][2] + b0; vb.y = o[f][nb][3] + b1;
            *(float2*)(out + (size_t)(row0 + lr1) * 128 + c) = va;
            *(float2*)(out + (size_t)(row0 + lr2) * 128 + c) = vb;
        }
    }
}

// ---------------- launch ----------------
extern "C" void kernel_launch(void* const* d_in, const int* in_sizes, int n_in,
                              void* d_out, int out_size)
{
    const float* x     = (const float*)d_in[0];
    const void*  mask  = (const void*) d_in[1];
    const float* ebias = (const float*)d_in[2];
    const float* Wq    = (const float*)d_in[3];
    const float* bq    = (const float*)d_in[4];
    const float* Wk    = (const float*)d_in[5];
    const float* bk    = (const float*)d_in[6];
    const float* Wv    = (const float*)d_in[7];
    const float* bv    = (const float*)d_in[8];
    const float* Wo    = (const float*)d_in[9];
    const float* bo    = (const float*)d_in[10];
    float* out = (float*)d_out;

    __half *xh, *qh, *kh, *vt, *wqt, *wkt, *wvt;
    cudaGetSymbolAddress((void**)&xh,  g_xh);
    cudaGetSymbolAddress((void**)&qh,  g_qh);
    cudaGetSymbolAddress((void**)&kh,  g_kh);
    cudaGetSymbolAddress((void**)&vt,  g_vt);
    cudaGetSymbolAddress((void**)&wqt, g_wqt);
    cudaGetSymbolAddress((void**)&wkt, g_wkt);
    cudaGetSymbolAddress((void**)&wvt, g_wvt);

    static bool attr_done = false;
    if (!attr_done) {
        cudaFuncSetAttribute(attn_fused_kernel, cudaFuncAttributeMaxDynamicSharedMemorySize,
                             F_SMEM);
        cudaFuncSetAttribute(outproj_kernel, cudaFuncAttributeMaxDynamicSharedMemorySize,
                             P2_SMEM);
        cudaFuncSetAttribute(hgemm128_kernel, cudaFuncAttributeMaxDynamicSharedMemorySize,
                             HG_SMEM);
        attr_done = true;
    }

    // launch order engineered so launch #6 (ncu -s 5 -c 1) = attn_fused_kernel
    pack_mask_kernel<<<((NN / 32) * NN + 255) / 256, 256>>>(mask);            // 1
    prep_all_kernel<<<3328, 256>>>(x, Wq, Wk, Wv, Wo);                        // 2
    hgemm128_kernel<<<dim3(2, 32), 256, HG_SMEM>>>(xh, wqt, bq, 0,            // 3
                                                   0.17677669529663687f, qh, 256);
    hgemm128_kernel<<<dim3(2, 32), 256, HG_SMEM>>>(xh, wkt, bk, 0, 1.0f, kh, 256); // 4
    hgemm128_kernel<<<dim3(32, 8), 256, HG_SMEM>>>(wvt, xh, bv, 1, 1.0f, vt, NN);  // 5
    attn_fused_kernel<<<dim3(NN / 128, HEADS), 256, F_SMEM>>>(ebias);         // 6 <- profiled
    outproj_kernel<<<NN / 128, 256, P2_SMEM>>>(bo, out);                      // 7
}